// round 1
// baseline (speedup 1.0000x reference)
#include <cuda_runtime.h>
#include <math_constants.h>

#define BATCH 4
#define SEQ   2048
#define DM    1024
#define NH    16
#define HD    64
#define NROWS (BATCH*SEQ)   // 8192
#define N_QKV (3*DM)        // 3072

// ---- scratch (device globals: allocation-free) ----
__device__ float g_q[BATCH*NH*SEQ*HD];      // [B,H,S,hd] rope'd
__device__ float g_k[BATCH*NH*SEQ*HD];
__device__ float g_v[BATCH*NH*SEQ*HD];
__device__ float g_attn[NROWS*DM];          // [B,S,D]
__device__ float g_cos[SEQ*(HD/2)];
__device__ float g_sin[SEQ*(HD/2)];

// ============================================================
// RoPE cos/sin table (accurate sincosf, args up to ~2048 rad)
// ============================================================
__global__ void rope_table_kernel() {
    int idx = blockIdx.x * blockDim.x + threadIdx.x;
    if (idx >= SEQ * (HD/2)) return;
    int s = idx >> 5;         // / 32
    int i = idx & 31;
    float inv = powf(10000.0f, -2.0f * (float)i / (float)HD);
    float ang = (float)s * inv;
    float sn, cs;
    sincosf(ang, &sn, &cs);
    g_cos[idx] = cs;
    g_sin[idx] = sn;
}

// ============================================================
// QKV GEMM: C[8192,3072] = x[8192,1024] @ w_qkv[3072,1024]^T
// 128x128x16 tiles, 256 threads, 8x8 microtile.
// Epilogue: RoPE on q/k, scatter to [B,H,S,hd] buffers.
// ============================================================
__global__ __launch_bounds__(256) void qkv_gemm(const float* __restrict__ x,
                                                const float* __restrict__ w) {
    __shared__ float As[16][128];
    __shared__ float Bs[16][128];
    const int tid = threadIdx.x;
    const int tn = tid & 15, tm = tid >> 4;
    const int bm = blockIdx.y, bn = blockIdx.x;

    float acc[8][8];
#pragma unroll
    for (int i = 0; i < 8; i++)
#pragma unroll
        for (int j = 0; j < 8; j++) acc[i][j] = 0.f;

    const int lrow = tid >> 2;          // 0..63
    const int lcol = (tid & 3) << 2;    // 0,4,8,12
    const float* Ap = x + (bm*128 + lrow)*DM + lcol;
    const float* Bp = w + (bn*128 + lrow)*DM + lcol;

    for (int k0 = 0; k0 < DM; k0 += 16) {
#pragma unroll
        for (int r = 0; r < 2; r++) {
            float4 av = *(const float4*)(Ap + r*64*DM + k0);
            float4 bv = *(const float4*)(Bp + r*64*DM + k0);
            As[lcol+0][lrow+r*64] = av.x;
            As[lcol+1][lrow+r*64] = av.y;
            As[lcol+2][lrow+r*64] = av.z;
            As[lcol+3][lrow+r*64] = av.w;
            Bs[lcol+0][lrow+r*64] = bv.x;
            Bs[lcol+1][lrow+r*64] = bv.y;
            Bs[lcol+2][lrow+r*64] = bv.z;
            Bs[lcol+3][lrow+r*64] = bv.w;
        }
        __syncthreads();
#pragma unroll
        for (int kk = 0; kk < 16; kk++) {
            float a[8], b[8];
            *(float4*)&a[0] = *(const float4*)&As[kk][tm*4];
            *(float4*)&a[4] = *(const float4*)&As[kk][tm*4+64];
            *(float4*)&b[0] = *(const float4*)&Bs[kk][tn*4];
            *(float4*)&b[4] = *(const float4*)&Bs[kk][tn*4+64];
#pragma unroll
            for (int i = 0; i < 8; i++)
#pragma unroll
                for (int j = 0; j < 8; j++)
                    acc[i][j] = fmaf(a[i], b[j], acc[i][j]);
        }
        __syncthreads();
    }

    // Epilogue: f = global output column = row of w_qkv.
    // sect 0 -> q (rope), 1 -> k (rope), 2 -> v (copy).
#pragma unroll
    for (int i = 0; i < 8; i++) {
        const int m  = bm*128 + tm*4 + ((i & 4) << 4) + (i & 3);
        const int bb = m >> 11;      // / 2048
        const int s  = m & 2047;
#pragma unroll
        for (int g = 0; g < 2; g++) {
            const int f0 = bn*128 + tn*4 + g*64;
            const float c0 = acc[i][g*4+0], c1 = acc[i][g*4+1];
            const float c2 = acc[i][g*4+2], c3 = acc[i][g*4+3];
            const int sect = f0 >> 10;
            const int rem  = f0 & 1023;
            const int h    = rem >> 6;
            const int d0   = rem & 63;
            const int base = ((bb*NH + h)*SEQ + s)*HD + d0;
            if (sect == 2) {
                *(float4*)&g_v[base] = make_float4(c0, c1, c2, c3);
            } else {
                const int p0 = (s << 5) + (d0 >> 1);
                const float cs0 = g_cos[p0],   sn0 = g_sin[p0];
                const float cs1 = g_cos[p0+1], sn1 = g_sin[p0+1];
                float4 o = make_float4(c0*cs0 - c1*sn0,
                                       c0*sn0 + c1*cs0,
                                       c2*cs1 - c3*sn1,
                                       c2*sn1 + c3*cs1);
                if (sect == 0) *(float4*)&g_q[base] = o;
                else           *(float4*)&g_k[base] = o;
            }
        }
    }
}

// ============================================================
// Flash attention (fp32): per-CTA (b, h, 64-query tile).
// 64x64 kv tiles, online softmax, causal (only j <= qb).
// ============================================================
#define PADW 68
#define SMEM_ATTN ((4*64*PADW + 3*64) * 4 + 64 * 4)

__global__ __launch_bounds__(256) void attn_kernel(const int* __restrict__ pmask_g) {
    extern __shared__ float sm[];
    float* Qs  = sm;
    float* Ks  = sm + 64*PADW;
    float* Vs  = sm + 2*64*PADW;
    float* Ss  = sm + 3*64*PADW;
    float* m_s = sm + 4*64*PADW;
    float* l_s = m_s + 64;
    float* a_s = l_s + 64;
    int*   pm  = (int*)(a_s + 64);

    const int qb = blockIdx.x, h = blockIdx.y, b = blockIdx.z;
    const int tid = threadIdx.x, tn = tid & 15, tm = tid >> 4;

    const float* Qg = g_q + ((b*NH + h)*SEQ + qb*64)*HD;
    const float* Kg = g_k + ((b*NH + h)*SEQ)*HD;
    const float* Vg = g_v + ((b*NH + h)*SEQ)*HD;

#pragma unroll
    for (int t = 0; t < 4; t++) {
        int slot = tid + t*256;
        int row = slot >> 4, c4 = (slot & 15) << 2;
        *(float4*)&Qs[row*PADW + c4] = *(const float4*)(Qg + row*HD + c4);
    }
    if (tid < 64) { m_s[tid] = -CUDART_INF_F; l_s[tid] = 0.f; }

    float O[4][4];
#pragma unroll
    for (int r = 0; r < 4; r++)
#pragma unroll
        for (int c = 0; c < 4; c++) O[r][c] = 0.f;

    for (int jt = 0; jt <= qb; jt++) {
        const float* Kt = Kg + jt*64*HD;
        const float* Vt = Vg + jt*64*HD;
#pragma unroll
        for (int t = 0; t < 4; t++) {
            int slot = tid + t*256;
            int row = slot >> 4, c4 = (slot & 15) << 2;
            *(float4*)&Ks[row*PADW + c4] = *(const float4*)(Kt + row*HD + c4);
            *(float4*)&Vs[row*PADW + c4] = *(const float4*)(Vt + row*HD + c4);
        }
        if (tid < 64) pm[tid] = pmask_g[b*SEQ + jt*64 + tid];
        __syncthreads();

        // S = Q K^T  (4x4 per thread; rows r*16+tm, cols c*16+tn)
        float acc[4][4];
#pragma unroll
        for (int r = 0; r < 4; r++)
#pragma unroll
            for (int c = 0; c < 4; c++) acc[r][c] = 0.f;

        for (int d = 0; d < HD; d += 4) {
            float4 qv[4], kv[4];
#pragma unroll
            for (int r = 0; r < 4; r++) qv[r] = *(const float4*)&Qs[(r*16+tm)*PADW + d];
#pragma unroll
            for (int c = 0; c < 4; c++) kv[c] = *(const float4*)&Ks[(c*16+tn)*PADW + d];
#pragma unroll
            for (int r = 0; r < 4; r++)
#pragma unroll
                for (int c = 0; c < 4; c++) {
                    acc[r][c] = fmaf(qv[r].x, kv[c].x, acc[r][c]);
                    acc[r][c] = fmaf(qv[r].y, kv[c].y, acc[r][c]);
                    acc[r][c] = fmaf(qv[r].z, kv[c].z, acc[r][c]);
                    acc[r][c] = fmaf(qv[r].w, kv[c].w, acc[r][c]);
                }
        }

        const bool diag = (jt == qb);
#pragma unroll
        for (int r = 0; r < 4; r++) {
            const int qr = r*16 + tm;
            const int qg = qb*64 + qr;
#pragma unroll
            for (int c = 0; c < 4; c++) {
                const int kc = c*16 + tn;
                const int kg = jt*64 + kc;
                float sv = acc[r][c] * 0.125f;   // 1/sqrt(64)
                if ((diag && kg > qg) || pm[kc] == 0) sv = -CUDART_INF_F;
                Ss[qr*PADW + kc] = sv;
            }
        }
        __syncthreads();

        // Row pass: online softmax stats + exponentiate in place
        if (tid < 64) {
            const float mold = m_s[tid];
            float mx = mold;
            float* srow = &Ss[tid*PADW];
#pragma unroll 8
            for (int k2 = 0; k2 < 64; k2++) mx = fmaxf(mx, srow[k2]);
            const float msafe = (mx == -CUDART_INF_F) ? 0.f : mx;
            float sum = 0.f;
#pragma unroll 8
            for (int k2 = 0; k2 < 64; k2++) {
                float p = __expf(srow[k2] - msafe);
                srow[k2] = p;
                sum += p;
            }
            const float al = __expf(mold - msafe);   // 0 when mold = -inf
            l_s[tid] = l_s[tid]*al + sum;
            m_s[tid] = mx;
            a_s[tid] = al;
        }
        __syncthreads();

        // O = diag(alpha) O + P V   (cols tn*4 .. tn*4+3)
#pragma unroll
        for (int r = 0; r < 4; r++) {
            const float al = a_s[r*16 + tm];
#pragma unroll
            for (int c = 0; c < 4; c++) O[r][c] *= al;
        }
        for (int kk = 0; kk < 64; kk += 4) {
            float4 vv[4];
#pragma unroll
            for (int u = 0; u < 4; u++) vv[u] = *(const float4*)&Vs[(kk+u)*PADW + tn*4];
#pragma unroll
            for (int r = 0; r < 4; r++) {
                const float* pr = &Ss[(r*16+tm)*PADW + kk];
                const float p0 = pr[0], p1 = pr[1], p2 = pr[2], p3 = pr[3];
                O[r][0] = fmaf(p0, vv[0].x, O[r][0]);
                O[r][0] = fmaf(p1, vv[1].x, O[r][0]);
                O[r][0] = fmaf(p2, vv[2].x, O[r][0]);
                O[r][0] = fmaf(p3, vv[3].x, O[r][0]);
                O[r][1] = fmaf(p0, vv[0].y, O[r][1]);
                O[r][1] = fmaf(p1, vv[1].y, O[r][1]);
                O[r][1] = fmaf(p2, vv[2].y, O[r][1]);
                O[r][1] = fmaf(p3, vv[3].y, O[r][1]);
                O[r][2] = fmaf(p0, vv[0].z, O[r][2]);
                O[r][2] = fmaf(p1, vv[1].z, O[r][2]);
                O[r][2] = fmaf(p2, vv[2].z, O[r][2]);
                O[r][2] = fmaf(p3, vv[3].z, O[r][2]);
                O[r][3] = fmaf(p0, vv[0].w, O[r][3]);
                O[r][3] = fmaf(p1, vv[1].w, O[r][3]);
                O[r][3] = fmaf(p2, vv[2].w, O[r][3]);
                O[r][3] = fmaf(p3, vv[3].w, O[r][3]);
            }
        }
        __syncthreads();
    }

    // Normalize and write to [B,S,H*hd] layout (ready for O-proj GEMM)
#pragma unroll
    for (int r = 0; r < 4; r++) {
        const int qr = r*16 + tm;
        const float linv = 1.f / l_s[qr];
        const int sg = qb*64 + qr;
        float4 o = make_float4(O[r][0]*linv, O[r][1]*linv, O[r][2]*linv, O[r][3]*linv);
        *(float4*)&g_attn[(b*SEQ + sg)*DM + h*HD + tn*4] = o;
    }
}

// ============================================================
// Output projection: out[8192,1024] = g_attn @ w_o[1024,1024]^T
// ============================================================
__global__ __launch_bounds__(256) void oproj_gemm(const float* __restrict__ w,
                                                  float* __restrict__ out) {
    __shared__ float As[16][128];
    __shared__ float Bs[16][128];
    const int tid = threadIdx.x;
    const int tn = tid & 15, tm = tid >> 4;
    const int bm = blockIdx.y, bn = blockIdx.x;

    float acc[8][8];
#pragma unroll
    for (int i = 0; i < 8; i++)
#pragma unroll
        for (int j = 0; j < 8; j++) acc[i][j] = 0.f;

    const int lrow = tid >> 2;
    const int lcol = (tid & 3) << 2;
    const float* Ap = g_attn + (bm*128 + lrow)*DM + lcol;
    const float* Bp = w      + (bn*128 + lrow)*DM + lcol;

    for (int k0 = 0; k0 < DM; k0 += 16) {
#pragma unroll
        for (int r = 0; r < 2; r++) {
            float4 av = *(const float4*)(Ap + r*64*DM + k0);
            float4 bv = *(const float4*)(Bp + r*64*DM + k0);
            As[lcol+0][lrow+r*64] = av.x;
            As[lcol+1][lrow+r*64] = av.y;
            As[lcol+2][lrow+r*64] = av.z;
            As[lcol+3][lrow+r*64] = av.w;
            Bs[lcol+0][lrow+r*64] = bv.x;
            Bs[lcol+1][lrow+r*64] = bv.y;
            Bs[lcol+2][lrow+r*64] = bv.z;
            Bs[lcol+3][lrow+r*64] = bv.w;
        }
        __syncthreads();
#pragma unroll
        for (int kk = 0; kk < 16; kk++) {
            float a[8], b[8];
            *(float4*)&a[0] = *(const float4*)&As[kk][tm*4];
            *(float4*)&a[4] = *(const float4*)&As[kk][tm*4+64];
            *(float4*)&b[0] = *(const float4*)&Bs[kk][tn*4];
            *(float4*)&b[4] = *(const float4*)&Bs[kk][tn*4+64];
#pragma unroll
            for (int i = 0; i < 8; i++)
#pragma unroll
                for (int j = 0; j < 8; j++)
                    acc[i][j] = fmaf(a[i], b[j], acc[i][j]);
        }
        __syncthreads();
    }

#pragma unroll
    for (int i = 0; i < 8; i++) {
        const int m = bm*128 + tm*4 + ((i & 4) << 4) + (i & 3);
#pragma unroll
        for (int g = 0; g < 2; g++) {
            const int n0 = bn*128 + tn*4 + g*64;
            *(float4*)&out[m*DM + n0] =
                make_float4(acc[i][g*4+0], acc[i][g*4+1], acc[i][g*4+2], acc[i][g*4+3]);
        }
    }
}

// ============================================================
extern "C" void kernel_launch(void* const* d_in, const int* in_sizes, int n_in,
                              void* d_out, int out_size) {
    const float* x      = (const float*)d_in[0];
    const int*   pmask  = (const int*)  d_in[1];
    const float* w_qkv  = (const float*)d_in[2];
    const float* w_o    = (const float*)d_in[3];
    float*       out    = (float*)d_out;

    cudaFuncSetAttribute(attn_kernel,
                         cudaFuncAttributeMaxDynamicSharedMemorySize, SMEM_ATTN);

    rope_table_kernel<<<256, 256>>>();
    qkv_gemm<<<dim3(N_QKV/128, NROWS/128), 256>>>(x, w_qkv);
    attn_kernel<<<dim3(SEQ/64, NH, BATCH), 256, SMEM_ATTN>>>(pmask);
    oproj_gemm<<<dim3(DM/128, NROWS/128), 256>>>(w_o, out);
}

// round 9
// speedup vs baseline: 1.3494x; 1.3494x over previous
#include <cuda_runtime.h>
#include <cuda_bf16.h>
#include <math_constants.h>
#include <cstdint>

#define BATCH 4
#define SEQ   2048
#define DM    1024
#define NH    16
#define HD    64
#define NROWS (BATCH*SEQ)   // 8192
#define N_QKV (3*DM)        // 3072

// ---- scratch (device globals; referenced ONLY from device code) ----
__device__ __align__(16) float g_q[BATCH*NH*SEQ*HD];
__device__ __align__(16) float g_k[BATCH*NH*SEQ*HD];
__device__ __align__(16) float g_v[BATCH*NH*SEQ*HD];
__device__ __align__(16) float g_cos[SEQ*(HD/2)];
__device__ __align__(16) float g_sin[SEQ*(HD/2)];
__device__ __align__(16) __nv_bfloat16 g_xh[NROWS*DM],  g_xl[NROWS*DM];
__device__ __align__(16) __nv_bfloat16 g_wqh[N_QKV*DM], g_wql[N_QKV*DM];
__device__ __align__(16) __nv_bfloat16 g_woh[DM*DM],    g_wol[DM*DM];
__device__ __align__(16) __nv_bfloat16 g_ah[NROWS*DM],  g_al[NROWS*DM];

// ============================================================
__device__ __forceinline__ void mma16816(float* c, const uint32_t* a,
                                         uint32_t b0, uint32_t b1) {
    asm volatile(
        "mma.sync.aligned.m16n8k16.row.col.f32.bf16.bf16.f32 "
        "{%0,%1,%2,%3}, {%4,%5,%6,%7}, {%8,%9}, {%0,%1,%2,%3};"
        : "+f"(c[0]), "+f"(c[1]), "+f"(c[2]), "+f"(c[3])
        : "r"(a[0]), "r"(a[1]), "r"(a[2]), "r"(a[3]), "r"(b0), "r"(b1));
}

// ============================================================
// RoPE cos/sin table
// ============================================================
__global__ void rope_table_kernel() {
    int idx = blockIdx.x * blockDim.x + threadIdx.x;
    if (idx >= SEQ * (HD/2)) return;
    int s = idx >> 5;
    int i = idx & 31;
    float inv = powf(10000.0f, -2.0f * (float)i / (float)HD);
    float ang = (float)s * inv;
    float sn, cs;
    sincosf(ang, &sn, &cs);
    g_cos[idx] = cs;
    g_sin[idx] = sn;
}

// ============================================================
// fp32 -> (bf16 hi, bf16 lo) split. WHICH selects dst globals:
// 0: x -> g_xh/g_xl   1: w_qkv -> g_wqh/g_wql   2: w_o -> g_woh/g_wol
// ============================================================
template<int WHICH>
__global__ void split_kernel(const float* __restrict__ src, int n4) {
    __nv_bfloat16* dh = (WHICH == 0) ? g_xh : (WHICH == 1) ? g_wqh : g_woh;
    __nv_bfloat16* dl = (WHICH == 0) ? g_xl : (WHICH == 1) ? g_wql : g_wol;
    int i = blockIdx.x * blockDim.x + threadIdx.x;
    if (i >= n4) return;
    float4 v = ((const float4*)src)[i];
    __nv_bfloat16 h0 = __float2bfloat16(v.x), h1 = __float2bfloat16(v.y);
    __nv_bfloat16 h2 = __float2bfloat16(v.z), h3 = __float2bfloat16(v.w);
    __nv_bfloat16 l0 = __float2bfloat16(v.x - __bfloat162float(h0));
    __nv_bfloat16 l1 = __float2bfloat16(v.y - __bfloat162float(h1));
    __nv_bfloat16 l2 = __float2bfloat16(v.z - __bfloat162float(h2));
    __nv_bfloat16 l3 = __float2bfloat16(v.w - __bfloat162float(h3));
    __nv_bfloat162* ph = (__nv_bfloat162*)(dh + i*4);
    __nv_bfloat162* pl = (__nv_bfloat162*)(dl + i*4);
    ph[0] = __halves2bfloat162(h0, h1);
    ph[1] = __halves2bfloat162(h2, h3);
    pl[0] = __halves2bfloat162(l0, l1);
    pl[1] = __halves2bfloat162(l2, l3);
}

// ============================================================
// HMMA GEMM: C[128,128] = A[128,K] @ B[N,K]^T, K=1024.
// 3 passes (AhBh + AhBl + AlBh), fp32 accum, mma m16n8k16.
// MODE 0: A=g_xh/g_xl, B=g_wqh/g_wql; epilogue RoPE -> g_q/g_k/g_v
// MODE 1: A=g_ah/g_al, B=g_woh/g_wol; epilogue fp32 -> out
// ============================================================
#define STRIDE_B  80                     // smem bytes/row (conflict-free frag loads)
#define CHUNK_K   32                     // bf16 K elems per chunk (64B/row)
#define OP_BYTES  (128*STRIDE_B)         // 10240
#define STG_BYTES (2*OP_BYTES)           // 20480 per buffer
#define NCHUNK    96
#define SMEM_GEMM (2*STG_BYTES)          // 40960

template<int MODE>
__global__ __launch_bounds__(256) void gemm_mma(float* __restrict__ out) {
    const __nv_bfloat16* __restrict__ Ah = (MODE == 0) ? g_xh  : g_ah;
    const __nv_bfloat16* __restrict__ Al = (MODE == 0) ? g_xl  : g_al;
    const __nv_bfloat16* __restrict__ Bh = (MODE == 0) ? g_wqh : g_woh;
    const __nv_bfloat16* __restrict__ Bl = (MODE == 0) ? g_wql : g_wol;

    extern __shared__ char smc[];
    const int tid = threadIdx.x, lane = tid & 31, wid = tid >> 5;
    const int warp_m = wid >> 2, warp_n = wid & 3;
    const int bm = blockIdx.y, bn = blockIdx.x;

    float acc[4][4][4];
#pragma unroll
    for (int mt = 0; mt < 4; mt++)
#pragma unroll
        for (int nt = 0; nt < 4; nt++)
#pragma unroll
            for (int q = 0; q < 4; q++) acc[mt][nt][q] = 0.f;

    // loader: seg = tid + s*256; tile = seg/512, row = (seg%512)/4, col = seg%4
    uint4 rg[4];
    auto gload = [&](int cc) {
        const int pass = cc >> 5, kc = cc & 31;
        const __nv_bfloat16* Ap = ((pass == 2) ? Al : Ah) + (size_t)bm*128*DM + kc*CHUNK_K;
        const __nv_bfloat16* Bp = ((pass == 1) ? Bl : Bh) + (size_t)bn*128*DM + kc*CHUNK_K;
#pragma unroll
        for (int s = 0; s < 4; s++) {
            const int seg = tid + s*256;
            const int r = (seg & 511) >> 2, c = seg & 3;
            const __nv_bfloat16* src = ((seg >> 9) ? Bp : Ap) + (size_t)r*DM + c*8;
            rg[s] = *(const uint4*)src;
        }
    };
    auto sstore = [&](int buf) {
#pragma unroll
        for (int s = 0; s < 4; s++) {
            const int seg = tid + s*256;
            const int r = (seg & 511) >> 2, c = seg & 3;
            *(uint4*)(smc + buf*STG_BYTES + (seg >> 9)*OP_BYTES + r*STRIDE_B + c*16) = rg[s];
        }
    };

    gload(0);
    sstore(0);
    __syncthreads();

    const int fr = lane >> 2;        // 0..7
    const int fcb = (lane & 3) * 4;  // byte offset of k-pair

    int cur = 0;
    for (int cc = 0; cc < NCHUNK; cc++) {
        if (cc + 1 < NCHUNK) gload(cc + 1);

        const char* sa = smc + cur*STG_BYTES + (warp_m*64 + fr)*STRIDE_B + fcb;
        const char* sb = smc + cur*STG_BYTES + OP_BYTES + (warp_n*32 + fr)*STRIDE_B + fcb;
#pragma unroll
        for (int ks = 0; ks < 2; ks++) {
            uint32_t a[4][4], b[4][2];
#pragma unroll
            for (int mt = 0; mt < 4; mt++) {
                const char* p = sa + mt*16*STRIDE_B + ks*32;
                a[mt][0] = *(const uint32_t*)(p);                    // m=fr,   k lo
                a[mt][1] = *(const uint32_t*)(p + 8*STRIDE_B);       // m=fr+8, k lo
                a[mt][2] = *(const uint32_t*)(p + 16);               // m=fr,   k hi
                a[mt][3] = *(const uint32_t*)(p + 8*STRIDE_B + 16);  // m=fr+8, k hi
            }
#pragma unroll
            for (int nt = 0; nt < 4; nt++) {
                const char* p = sb + nt*8*STRIDE_B + ks*32;
                b[nt][0] = *(const uint32_t*)(p);                    // n=fr, k lo
                b[nt][1] = *(const uint32_t*)(p + 16);               // n=fr, k hi
            }
#pragma unroll
            for (int mt = 0; mt < 4; mt++)
#pragma unroll
                for (int nt = 0; nt < 4; nt++)
                    mma16816(acc[mt][nt], a[mt], b[nt][0], b[nt][1]);
        }

        if (cc + 1 < NCHUNK) sstore(cur ^ 1);
        __syncthreads();
        cur ^= 1;
    }

    // ---- epilogue (C frag: rows lane/4, lane/4+8; cols 2*(lane%4)+{0,1}) ----
#pragma unroll
    for (int mt = 0; mt < 4; mt++) {
#pragma unroll
        for (int nt = 0; nt < 4; nt++) {
            const int rr = warp_m*64 + mt*16 + (lane >> 2);
            const int cc2 = warp_n*32 + nt*8 + 2*(lane & 3);
            const int f = bn*128 + cc2;
#pragma unroll
            for (int h2 = 0; h2 < 2; h2++) {
                const int m = bm*128 + rr + h2*8;
                const float v0 = acc[mt][nt][h2*2], v1 = acc[mt][nt][h2*2+1];
                if (MODE == 0) {
                    const int b = m >> 11, s = m & 2047;
                    const int sect = f >> 10, rem = f & 1023;
                    const int hh = rem >> 6, d0 = rem & 63;
                    const size_t base = (((size_t)b*NH + hh)*SEQ + s)*HD + d0;
                    if (sect == 2) {
                        *(float2*)&g_v[base] = make_float2(v0, v1);
                    } else {
                        const int p0 = (s << 5) + (d0 >> 1);
                        const float cs = g_cos[p0], sn = g_sin[p0];
                        float2 o = make_float2(v0*cs - v1*sn, v0*sn + v1*cs);
                        if (sect == 0) *(float2*)&g_q[base] = o;
                        else           *(float2*)&g_k[base] = o;
                    }
                } else {
                    *(float2*)&out[(size_t)m*DM + f] = make_float2(v0, v1);
                }
            }
        }
    }
}

// ============================================================
// Flash attention (fp32 FFMA): per-CTA (b, h, 64-query tile).
// ============================================================
#define PADW 68
#define SMEM_ATTN ((4*64*PADW + 3*64) * 4 + 64 * 4)

__global__ __launch_bounds__(256) void attn_kernel(const int* __restrict__ pmask_g) {
    extern __shared__ float smf[];
    float* Qs  = smf;
    float* Ks  = smf + 64*PADW;
    float* Vs  = smf + 2*64*PADW;
    float* Ss  = smf + 3*64*PADW;
    float* m_s = smf + 4*64*PADW;
    float* l_s = m_s + 64;
    float* a_s = l_s + 64;
    int*   pm  = (int*)(a_s + 64);

    const int qb = blockIdx.x, h = blockIdx.y, b = blockIdx.z;
    const int tid = threadIdx.x, tn = tid & 15, tm = tid >> 4;

    const float* Qg = g_q + ((b*NH + h)*SEQ + qb*64)*HD;
    const float* Kg = g_k + ((b*NH + h)*SEQ)*HD;
    const float* Vg = g_v + ((b*NH + h)*SEQ)*HD;

#pragma unroll
    for (int t = 0; t < 4; t++) {
        int slot = tid + t*256;
        int row = slot >> 4, c4 = (slot & 15) << 2;
        *(float4*)&Qs[row*PADW + c4] = *(const float4*)(Qg + row*HD + c4);
    }
    if (tid < 64) { m_s[tid] = -CUDART_INF_F; l_s[tid] = 0.f; }

    float O[4][4];
#pragma unroll
    for (int r = 0; r < 4; r++)
#pragma unroll
        for (int c = 0; c < 4; c++) O[r][c] = 0.f;

    for (int jt = 0; jt <= qb; jt++) {
        const float* Kt = Kg + jt*64*HD;
        const float* Vt = Vg + jt*64*HD;
#pragma unroll
        for (int t = 0; t < 4; t++) {
            int slot = tid + t*256;
            int row = slot >> 4, c4 = (slot & 15) << 2;
            *(float4*)&Ks[row*PADW + c4] = *(const float4*)(Kt + row*HD + c4);
            *(float4*)&Vs[row*PADW + c4] = *(const float4*)(Vt + row*HD + c4);
        }
        if (tid < 64) pm[tid] = pmask_g[b*SEQ + jt*64 + tid];
        __syncthreads();

        float acc[4][4];
#pragma unroll
        for (int r = 0; r < 4; r++)
#pragma unroll
            for (int c = 0; c < 4; c++) acc[r][c] = 0.f;

        for (int d = 0; d < HD; d += 4) {
            float4 qv[4], kv[4];
#pragma unroll
            for (int r = 0; r < 4; r++) qv[r] = *(const float4*)&Qs[(r*16+tm)*PADW + d];
#pragma unroll
            for (int c = 0; c < 4; c++) kv[c] = *(const float4*)&Ks[(c*16+tn)*PADW + d];
#pragma unroll
            for (int r = 0; r < 4; r++)
#pragma unroll
                for (int c = 0; c < 4; c++) {
                    acc[r][c] = fmaf(qv[r].x, kv[c].x, acc[r][c]);
                    acc[r][c] = fmaf(qv[r].y, kv[c].y, acc[r][c]);
                    acc[r][c] = fmaf(qv[r].z, kv[c].z, acc[r][c]);
                    acc[r][c] = fmaf(qv[r].w, kv[c].w, acc[r][c]);
                }
        }

        const bool diag = (jt == qb);
#pragma unroll
        for (int r = 0; r < 4; r++) {
            const int qr = r*16 + tm;
            const int qg = qb*64 + qr;
#pragma unroll
            for (int c = 0; c < 4; c++) {
                const int kc = c*16 + tn;
                const int kg = jt*64 + kc;
                float sv = acc[r][c] * 0.125f;
                if ((diag && kg > qg) || pm[kc] == 0) sv = -CUDART_INF_F;
                Ss[qr*PADW + kc] = sv;
            }
        }
        __syncthreads();

        if (tid < 64) {
            const float mold = m_s[tid];
            float mx = mold;
            float* srow = &Ss[tid*PADW];
#pragma unroll 8
            for (int k2 = 0; k2 < 64; k2++) mx = fmaxf(mx, srow[k2]);
            const float msafe = (mx == -CUDART_INF_F) ? 0.f : mx;
            float sum = 0.f;
#pragma unroll 8
            for (int k2 = 0; k2 < 64; k2++) {
                float p = __expf(srow[k2] - msafe);
                srow[k2] = p;
                sum += p;
            }
            const float al = __expf(mold - msafe);
            l_s[tid] = l_s[tid]*al + sum;
            m_s[tid] = mx;
            a_s[tid] = al;
        }
        __syncthreads();

#pragma unroll
        for (int r = 0; r < 4; r++) {
            const float al = a_s[r*16 + tm];
#pragma unroll
            for (int c = 0; c < 4; c++) O[r][c] *= al;
        }
        for (int kk = 0; kk < 64; kk += 4) {
            float4 vv[4];
#pragma unroll
            for (int u = 0; u < 4; u++) vv[u] = *(const float4*)&Vs[(kk+u)*PADW + tn*4];
#pragma unroll
            for (int r = 0; r < 4; r++) {
                const float* pr = &Ss[(r*16+tm)*PADW + kk];
                const float p0 = pr[0], p1 = pr[1], p2 = pr[2], p3 = pr[3];
                O[r][0] = fmaf(p0, vv[0].x, O[r][0]);
                O[r][0] = fmaf(p1, vv[1].x, O[r][0]);
                O[r][0] = fmaf(p2, vv[2].x, O[r][0]);
                O[r][0] = fmaf(p3, vv[3].x, O[r][0]);
                O[r][1] = fmaf(p0, vv[0].y, O[r][1]);
                O[r][1] = fmaf(p1, vv[1].y, O[r][1]);
                O[r][1] = fmaf(p2, vv[2].y, O[r][1]);
                O[r][1] = fmaf(p3, vv[3].y, O[r][1]);
                O[r][2] = fmaf(p0, vv[0].z, O[r][2]);
                O[r][2] = fmaf(p1, vv[1].z, O[r][2]);
                O[r][2] = fmaf(p2, vv[2].z, O[r][2]);
                O[r][2] = fmaf(p3, vv[3].z, O[r][2]);
                O[r][3] = fmaf(p0, vv[0].w, O[r][3]);
                O[r][3] = fmaf(p1, vv[1].w, O[r][3]);
                O[r][3] = fmaf(p2, vv[2].w, O[r][3]);
                O[r][3] = fmaf(p3, vv[3].w, O[r][3]);
            }
        }
        __syncthreads();
    }

    // Normalize; emit bf16 hi/lo for the HMMA O-projection
#pragma unroll
    for (int r = 0; r < 4; r++) {
        const int qr = r*16 + tm;
        const float linv = 1.f / l_s[qr];
        const int sg = qb*64 + qr;
        const size_t idx = ((size_t)b*SEQ + sg)*DM + h*HD + tn*4;
        float v[4];
#pragma unroll
        for (int c = 0; c < 4; c++) v[c] = O[r][c] * linv;
        __nv_bfloat16 hb[4], lb[4];
#pragma unroll
        for (int c = 0; c < 4; c++) {
            hb[c] = __float2bfloat16(v[c]);
            lb[c] = __float2bfloat16(v[c] - __bfloat162float(hb[c]));
        }
        *(__nv_bfloat162*)&g_ah[idx]     = __halves2bfloat162(hb[0], hb[1]);
        *(__nv_bfloat162*)&g_ah[idx + 2] = __halves2bfloat162(hb[2], hb[3]);
        *(__nv_bfloat162*)&g_al[idx]     = __halves2bfloat162(lb[0], lb[1]);
        *(__nv_bfloat162*)&g_al[idx + 2] = __halves2bfloat162(lb[2], lb[3]);
    }
}

// ============================================================
extern "C" void kernel_launch(void* const* d_in, const int* in_sizes, int n_in,
                              void* d_out, int out_size) {
    const float* x      = (const float*)d_in[0];
    const int*   pmask  = (const int*)  d_in[1];
    const float* w_qkv  = (const float*)d_in[2];
    const float* w_o    = (const float*)d_in[3];
    float*       out    = (float*)d_out;

    cudaFuncSetAttribute(attn_kernel,
                         cudaFuncAttributeMaxDynamicSharedMemorySize, SMEM_ATTN);

    rope_table_kernel<<<256, 256>>>();
    split_kernel<0><<<(NROWS*DM/4 + 255)/256, 256>>>(x,     NROWS*DM/4);
    split_kernel<1><<<(N_QKV*DM/4 + 255)/256, 256>>>(w_qkv, N_QKV*DM/4);
    split_kernel<2><<<(DM*DM/4 + 255)/256, 256>>>(w_o,      DM*DM/4);

    gemm_mma<0><<<dim3(N_QKV/128, NROWS/128), 256, SMEM_GEMM>>>(nullptr);
    attn_kernel<<<dim3(SEQ/64, NH, BATCH), 256, SMEM_ATTN>>>(pmask);
    gemm_mma<1><<<dim3(DM/128, NROWS/128), 256, SMEM_GEMM>>>(out);
}

// round 12
// speedup vs baseline: 1.6850x; 1.2487x over previous
#include <cuda_runtime.h>
#include <cuda_bf16.h>
#include <math_constants.h>
#include <cstdint>

#define BATCH 4
#define SEQ   2048
#define DM    1024
#define NH    16
#define HD    64
#define NROWS (BATCH*SEQ)   // 8192
#define N_QKV (3*DM)        // 3072

// ---- scratch (device globals; referenced ONLY from device code) ----
__device__ __align__(16) float g_v[BATCH*NH*SEQ*HD];
__device__ __align__(16) float g_cos[SEQ*(HD/2)];
__device__ __align__(16) float g_sin[SEQ*(HD/2)];
__device__ __align__(16) __nv_bfloat16 g_qh[BATCH*NH*SEQ*HD], g_ql[BATCH*NH*SEQ*HD];
__device__ __align__(16) __nv_bfloat16 g_kh[BATCH*NH*SEQ*HD], g_kl[BATCH*NH*SEQ*HD];
__device__ __align__(16) __nv_bfloat16 g_xh[NROWS*DM],  g_xl[NROWS*DM];
__device__ __align__(16) __nv_bfloat16 g_wqh[N_QKV*DM], g_wql[N_QKV*DM];
__device__ __align__(16) __nv_bfloat16 g_woh[DM*DM],    g_wol[DM*DM];
__device__ __align__(16) __nv_bfloat16 g_ah[NROWS*DM],  g_al[NROWS*DM];

// ============================================================
__device__ __forceinline__ void mma16816(float* c, const uint32_t* a,
                                         uint32_t b0, uint32_t b1) {
    asm volatile(
        "mma.sync.aligned.m16n8k16.row.col.f32.bf16.bf16.f32 "
        "{%0,%1,%2,%3}, {%4,%5,%6,%7}, {%8,%9}, {%0,%1,%2,%3};"
        : "+f"(c[0]), "+f"(c[1]), "+f"(c[2]), "+f"(c[3])
        : "r"(a[0]), "r"(a[1]), "r"(a[2]), "r"(a[3]), "r"(b0), "r"(b1));
}

// ============================================================
// RoPE cos/sin table
// ============================================================
__global__ void rope_table_kernel() {
    int idx = blockIdx.x * blockDim.x + threadIdx.x;
    if (idx >= SEQ * (HD/2)) return;
    int s = idx >> 5;
    int i = idx & 31;
    float inv = powf(10000.0f, -2.0f * (float)i / (float)HD);
    float ang = (float)s * inv;
    float sn, cs;
    sincosf(ang, &sn, &cs);
    g_cos[idx] = cs;
    g_sin[idx] = sn;
}

// ============================================================
// fp32 -> (bf16 hi, bf16 lo) split. WHICH selects dst globals.
// ============================================================
template<int WHICH>
__global__ void split_kernel(const float* __restrict__ src, int n4) {
    __nv_bfloat16* dh = (WHICH == 0) ? g_xh : (WHICH == 1) ? g_wqh : g_woh;
    __nv_bfloat16* dl = (WHICH == 0) ? g_xl : (WHICH == 1) ? g_wql : g_wol;
    int i = blockIdx.x * blockDim.x + threadIdx.x;
    if (i >= n4) return;
    float4 v = ((const float4*)src)[i];
    __nv_bfloat16 h0 = __float2bfloat16(v.x), h1 = __float2bfloat16(v.y);
    __nv_bfloat16 h2 = __float2bfloat16(v.z), h3 = __float2bfloat16(v.w);
    __nv_bfloat16 l0 = __float2bfloat16(v.x - __bfloat162float(h0));
    __nv_bfloat16 l1 = __float2bfloat16(v.y - __bfloat162float(h1));
    __nv_bfloat16 l2 = __float2bfloat16(v.z - __bfloat162float(h2));
    __nv_bfloat16 l3 = __float2bfloat16(v.w - __bfloat162float(h3));
    __nv_bfloat162* ph = (__nv_bfloat162*)(dh + i*4);
    __nv_bfloat162* pl = (__nv_bfloat162*)(dl + i*4);
    ph[0] = __halves2bfloat162(h0, h1);
    ph[1] = __halves2bfloat162(h2, h3);
    pl[0] = __halves2bfloat162(l0, l1);
    pl[1] = __halves2bfloat162(l2, l3);
}

// ============================================================
// HMMA GEMM (validated): C[128,128] = A[128,K] @ B[N,K]^T, K=1024.
// MODE 0: epilogue RoPE -> g_qh/g_ql, g_kh/g_kl (bf16 hi/lo), g_v fp32
// MODE 1: plain fp32 -> out
// ============================================================
#define STRIDE_B  80
#define CHUNK_K   32
#define OP_BYTES  (128*STRIDE_B)
#define STG_BYTES (2*OP_BYTES)
#define NCHUNK    96
#define SMEM_GEMM (2*STG_BYTES)

template<int MODE>
__global__ __launch_bounds__(256) void gemm_mma(float* __restrict__ out) {
    const __nv_bfloat16* __restrict__ Ah = (MODE == 0) ? g_xh  : g_ah;
    const __nv_bfloat16* __restrict__ Al = (MODE == 0) ? g_xl  : g_al;
    const __nv_bfloat16* __restrict__ Bh = (MODE == 0) ? g_wqh : g_woh;
    const __nv_bfloat16* __restrict__ Bl = (MODE == 0) ? g_wql : g_wol;

    extern __shared__ char smc[];
    const int tid = threadIdx.x, lane = tid & 31, wid = tid >> 5;
    const int warp_m = wid >> 2, warp_n = wid & 3;
    const int bm = blockIdx.y, bn = blockIdx.x;

    float acc[4][4][4];
#pragma unroll
    for (int mt = 0; mt < 4; mt++)
#pragma unroll
        for (int nt = 0; nt < 4; nt++)
#pragma unroll
            for (int q = 0; q < 4; q++) acc[mt][nt][q] = 0.f;

    uint4 rg[4];
    auto gload = [&](int cc) {
        const int pass = cc >> 5, kc = cc & 31;
        const __nv_bfloat16* Ap = ((pass == 2) ? Al : Ah) + (size_t)bm*128*DM + kc*CHUNK_K;
        const __nv_bfloat16* Bp = ((pass == 1) ? Bl : Bh) + (size_t)bn*128*DM + kc*CHUNK_K;
#pragma unroll
        for (int s = 0; s < 4; s++) {
            const int seg = tid + s*256;
            const int r = (seg & 511) >> 2, c = seg & 3;
            const __nv_bfloat16* src = ((seg >> 9) ? Bp : Ap) + (size_t)r*DM + c*8;
            rg[s] = *(const uint4*)src;
        }
    };
    auto sstore = [&](int buf) {
#pragma unroll
        for (int s = 0; s < 4; s++) {
            const int seg = tid + s*256;
            const int r = (seg & 511) >> 2, c = seg & 3;
            *(uint4*)(smc + buf*STG_BYTES + (seg >> 9)*OP_BYTES + r*STRIDE_B + c*16) = rg[s];
        }
    };

    gload(0);
    sstore(0);
    __syncthreads();

    const int fr = lane >> 2;
    const int fcb = (lane & 3) * 4;

    int cur = 0;
    for (int cc = 0; cc < NCHUNK; cc++) {
        if (cc + 1 < NCHUNK) gload(cc + 1);

        const char* sa = smc + cur*STG_BYTES + (warp_m*64 + fr)*STRIDE_B + fcb;
        const char* sb = smc + cur*STG_BYTES + OP_BYTES + (warp_n*32 + fr)*STRIDE_B + fcb;
#pragma unroll
        for (int ks = 0; ks < 2; ks++) {
            uint32_t a[4][4], b[4][2];
#pragma unroll
            for (int mt = 0; mt < 4; mt++) {
                const char* p = sa + mt*16*STRIDE_B + ks*32;
                a[mt][0] = *(const uint32_t*)(p);
                a[mt][1] = *(const uint32_t*)(p + 8*STRIDE_B);
                a[mt][2] = *(const uint32_t*)(p + 16);
                a[mt][3] = *(const uint32_t*)(p + 8*STRIDE_B + 16);
            }
#pragma unroll
            for (int nt = 0; nt < 4; nt++) {
                const char* p = sb + nt*8*STRIDE_B + ks*32;
                b[nt][0] = *(const uint32_t*)(p);
                b[nt][1] = *(const uint32_t*)(p + 16);
            }
#pragma unroll
            for (int mt = 0; mt < 4; mt++)
#pragma unroll
                for (int nt = 0; nt < 4; nt++)
                    mma16816(acc[mt][nt], a[mt], b[nt][0], b[nt][1]);
        }

        if (cc + 1 < NCHUNK) sstore(cur ^ 1);
        __syncthreads();
        cur ^= 1;
    }

    // ---- epilogue ----
#pragma unroll
    for (int mt = 0; mt < 4; mt++) {
#pragma unroll
        for (int nt = 0; nt < 4; nt++) {
            const int rr = warp_m*64 + mt*16 + (lane >> 2);
            const int cc2 = warp_n*32 + nt*8 + 2*(lane & 3);
            const int f = bn*128 + cc2;
#pragma unroll
            for (int h2 = 0; h2 < 2; h2++) {
                const int m = bm*128 + rr + h2*8;
                const float v0 = acc[mt][nt][h2*2], v1 = acc[mt][nt][h2*2+1];
                if (MODE == 0) {
                    const int b = m >> 11, s = m & 2047;
                    const int sect = f >> 10, rem = f & 1023;
                    const int hh = rem >> 6, d0 = rem & 63;
                    const size_t base = (((size_t)b*NH + hh)*SEQ + s)*HD + d0;
                    if (sect == 2) {
                        *(float2*)&g_v[base] = make_float2(v0, v1);
                    } else {
                        const int p0 = (s << 5) + (d0 >> 1);
                        const float cs = g_cos[p0], sn = g_sin[p0];
                        const float o0 = v0*cs - v1*sn, o1 = v0*sn + v1*cs;
                        __nv_bfloat16 h0 = __float2bfloat16(o0), h1 = __float2bfloat16(o1);
                        __nv_bfloat162 hi = __halves2bfloat162(h0, h1);
                        __nv_bfloat162 lo = __halves2bfloat162(
                            __float2bfloat16(o0 - __bfloat162float(h0)),
                            __float2bfloat16(o1 - __bfloat162float(h1)));
                        if (sect == 0) {
                            *(__nv_bfloat162*)&g_qh[base] = hi;
                            *(__nv_bfloat162*)&g_ql[base] = lo;
                        } else {
                            *(__nv_bfloat162*)&g_kh[base] = hi;
                            *(__nv_bfloat162*)&g_kl[base] = lo;
                        }
                    }
                } else {
                    *(float2*)&out[(size_t)m*DM + f] = make_float2(v0, v1);
                }
            }
        }
    }
}

// ============================================================
// HMMA flash attention: per-CTA (b, h, 64-query tile), 256 thr / 8 warps.
// QK^T and PV via mma.m16n8k16, 3-term bf16 split, fp32 accum.
// Warp tile: S/O rows 16*warp_m..+15, cols 32*warp_n..+31 (4 n-tiles of 8).
// ============================================================
#define AT_ROWB 144                    // 72 bf16 per smem row (conflict-free)
#define A_QH 0
#define A_QL (A_QH + 9216)
#define A_KH (A_QL + 9216)
#define A_KL (A_KH + 9216)
#define A_VH (A_KL + 9216)
#define A_VL (A_VH + 9216)
#define A_PH (A_VL + 9216)
#define A_PL (A_PH + 9216)
#define A_S  (A_PL + 9216)             // fp32 [64][68]
#define A_M  (A_S + 64*68*4)
#define A_L  (A_M + 256)
#define A_A  (A_L + 256)
#define A_PM (A_A + 256)
#define SMEM_ATTN (A_PM + 256)         // 92416

__global__ __launch_bounds__(256) void attn_kernel(const int* __restrict__ pmask_g) {
    extern __shared__ char sm[];
    float* Ss  = (float*)(sm + A_S);
    float* m_s = (float*)(sm + A_M);
    float* l_s = (float*)(sm + A_L);
    float* a_s = (float*)(sm + A_A);
    int*   pm  = (int*)(sm + A_PM);

    const int qb = blockIdx.x, h = blockIdx.y, b = blockIdx.z;
    const int tid = threadIdx.x, lane = tid & 31, wid = tid >> 5;
    const int warp_m = wid & 3, warp_n = wid >> 2;
    const int fr = lane >> 2;
    const int fcb = (lane & 3) * 4;

    const __nv_bfloat16* Qhg = g_qh + ((size_t)(b*NH + h)*SEQ + qb*64)*HD;
    const __nv_bfloat16* Qlg = g_ql + ((size_t)(b*NH + h)*SEQ + qb*64)*HD;
    const __nv_bfloat16* Khg = g_kh + ((size_t)(b*NH + h)*SEQ)*HD;
    const __nv_bfloat16* Klg = g_kl + ((size_t)(b*NH + h)*SEQ)*HD;
    const float*         Vg  = g_v  + ((size_t)(b*NH + h)*SEQ)*HD;

    // Q tiles (once)
#pragma unroll
    for (int t = 0; t < 2; t++) {
        const int seg = tid + t*256, r = seg >> 3, c = seg & 7;
        *(uint4*)(sm + A_QH + r*AT_ROWB + c*16) = *(const uint4*)(Qhg + r*HD + c*8);
        *(uint4*)(sm + A_QL + r*AT_ROWB + c*16) = *(const uint4*)(Qlg + r*HD + c*8);
    }
    if (tid < 64) { m_s[tid] = -CUDART_INF_F; l_s[tid] = 0.f; }

    float O[4][4];
#pragma unroll
    for (int nt = 0; nt < 4; nt++)
#pragma unroll
        for (int q = 0; q < 4; q++) O[nt][q] = 0.f;

    for (int jt = 0; jt <= qb; jt++) {
        // K tiles
#pragma unroll
        for (int t = 0; t < 2; t++) {
            const int seg = tid + t*256, r = seg >> 3, c = seg & 7;
            *(uint4*)(sm + A_KH + r*AT_ROWB + c*16) =
                *(const uint4*)(Khg + (size_t)(jt*64 + r)*HD + c*8);
            *(uint4*)(sm + A_KL + r*AT_ROWB + c*16) =
                *(const uint4*)(Klg + (size_t)(jt*64 + r)*HD + c*8);
        }
        // V: fp32 -> bf16 hi/lo, transposed (Vt[hd][key])
#pragma unroll
        for (int t = 0; t < 4; t++) {
            const int seg = tid + t*256, r = seg >> 4, c4 = (seg & 15) << 2;
            float4 v = *(const float4*)(Vg + (size_t)(jt*64 + r)*HD + c4);
            float vv[4] = {v.x, v.y, v.z, v.w};
#pragma unroll
            for (int j = 0; j < 4; j++) {
                const int col = c4 + j;
                __nv_bfloat16 hi = __float2bfloat16(vv[j]);
                *(__nv_bfloat16*)(sm + A_VH + col*AT_ROWB + r*2) = hi;
                *(__nv_bfloat16*)(sm + A_VL + col*AT_ROWB + r*2) =
                    __float2bfloat16(vv[j] - __bfloat162float(hi));
            }
        }
        if (tid < 64) pm[tid] = pmask_g[b*SEQ + jt*64 + tid];
        __syncthreads();

        // ---- S = Q K^T (3 passes) ----
        float sacc[4][4];
#pragma unroll
        for (int nt = 0; nt < 4; nt++)
#pragma unroll
            for (int q = 0; q < 4; q++) sacc[nt][q] = 0.f;

#pragma unroll
        for (int pass = 0; pass < 3; pass++) {
            const char* aB = sm + ((pass == 2) ? A_QL : A_QH)
                             + (warp_m*16 + fr)*AT_ROWB + fcb;
            const char* bB = sm + ((pass == 1) ? A_KL : A_KH) + fcb;
#pragma unroll
            for (int ks = 0; ks < 4; ks++) {
                uint32_t a[4];
                const char* pa = aB + ks*32;
                a[0] = *(const uint32_t*)(pa);
                a[1] = *(const uint32_t*)(pa + 8*AT_ROWB);
                a[2] = *(const uint32_t*)(pa + 16);
                a[3] = *(const uint32_t*)(pa + 8*AT_ROWB + 16);
#pragma unroll
                for (int nt = 0; nt < 4; nt++) {
                    const char* pb = bB + (warp_n*32 + nt*8 + fr)*AT_ROWB + ks*32;
                    mma16816(sacc[nt], a, *(const uint32_t*)pb,
                             *(const uint32_t*)(pb + 16));
                }
            }
        }

        // scale + mask -> S smem
        const bool diag = (jt == qb);
#pragma unroll
        for (int nt = 0; nt < 4; nt++) {
            const int c = warp_n*32 + nt*8 + 2*(lane & 3);
            const int kg0 = jt*64 + c, kg1 = kg0 + 1;
            const bool z0 = (pm[c] == 0), z1 = (pm[c+1] == 0);
#pragma unroll
            for (int h2 = 0; h2 < 2; h2++) {
                const int r = warp_m*16 + fr + h2*8;
                const int qg = qb*64 + r;
                float v0 = sacc[nt][h2*2]   * 0.125f;
                float v1 = sacc[nt][h2*2+1] * 0.125f;
                if ((diag && kg0 > qg) || z0) v0 = -CUDART_INF_F;
                if ((diag && kg1 > qg) || z1) v1 = -CUDART_INF_F;
                *(float2*)&Ss[r*68 + c] = make_float2(v0, v1);
            }
        }
        __syncthreads();

        // ---- softmax: 4 threads per row ----
        {
            const int row = tid >> 2, part = tid & 3;
            const float* srow = Ss + row*68 + part*16;
            float mx = -CUDART_INF_F;
#pragma unroll
            for (int i = 0; i < 16; i++) mx = fmaxf(mx, srow[i]);
            mx = fmaxf(mx, __shfl_xor_sync(0xffffffffu, mx, 1));
            mx = fmaxf(mx, __shfl_xor_sync(0xffffffffu, mx, 2));
            const float mold = m_s[row];
            mx = fmaxf(mx, mold);
            const float msafe = (mx == -CUDART_INF_F) ? 0.f : mx;
            float sum = 0.f;
            __nv_bfloat16* phr = (__nv_bfloat16*)(sm + A_PH + row*AT_ROWB) + part*16;
            __nv_bfloat16* plr = (__nv_bfloat16*)(sm + A_PL + row*AT_ROWB) + part*16;
#pragma unroll
            for (int i = 0; i < 16; i++) {
                const float p = __expf(srow[i] - msafe);
                sum += p;
                __nv_bfloat16 hi = __float2bfloat16(p);
                phr[i] = hi;
                plr[i] = __float2bfloat16(p - __bfloat162float(hi));
            }
            sum += __shfl_xor_sync(0xffffffffu, sum, 1);
            sum += __shfl_xor_sync(0xffffffffu, sum, 2);
            if (part == 0) {
                const float al = __expf(mold - msafe);
                l_s[row] = l_s[row]*al + sum;
                m_s[row] = mx;
                a_s[row] = al;
            }
        }
        __syncthreads();

        // ---- O = diag(alpha) O + P V (3 passes) ----
        {
            const float al0 = a_s[warp_m*16 + fr];
            const float al1 = a_s[warp_m*16 + fr + 8];
#pragma unroll
            for (int nt = 0; nt < 4; nt++) {
                O[nt][0] *= al0; O[nt][1] *= al0;
                O[nt][2] *= al1; O[nt][3] *= al1;
            }
#pragma unroll
            for (int pass = 0; pass < 3; pass++) {
                const char* aB = sm + ((pass == 2) ? A_PL : A_PH)
                                 + (warp_m*16 + fr)*AT_ROWB + fcb;
                const char* bB = sm + ((pass == 1) ? A_VL : A_VH) + fcb;
#pragma unroll
                for (int ks = 0; ks < 4; ks++) {
                    uint32_t a[4];
                    const char* pa = aB + ks*32;
                    a[0] = *(const uint32_t*)(pa);
                    a[1] = *(const uint32_t*)(pa + 8*AT_ROWB);
                    a[2] = *(const uint32_t*)(pa + 16);
                    a[3] = *(const uint32_t*)(pa + 8*AT_ROWB + 16);
#pragma unroll
                    for (int nt = 0; nt < 4; nt++) {
                        const char* pb = bB + (warp_n*32 + nt*8 + fr)*AT_ROWB + ks*32;
                        mma16816(O[nt], a, *(const uint32_t*)pb,
                                 *(const uint32_t*)(pb + 16));
                    }
                }
            }
        }
        __syncthreads();
    }

    // ---- epilogue: normalize, emit bf16 hi/lo for O-projection ----
    const float li0 = 1.f / l_s[warp_m*16 + fr];
    const float li1 = 1.f / l_s[warp_m*16 + fr + 8];
#pragma unroll
    for (int nt = 0; nt < 4; nt++) {
        const int colg = h*HD + warp_n*32 + nt*8 + 2*(lane & 3);
#pragma unroll
        for (int h2 = 0; h2 < 2; h2++) {
            const int r = warp_m*16 + fr + h2*8;
            const int sg = qb*64 + r;
            const float li = h2 ? li1 : li0;
            const float v0 = O[nt][h2*2]*li, v1 = O[nt][h2*2+1]*li;
            const size_t idx = ((size_t)b*SEQ + sg)*DM + colg;
            __nv_bfloat16 h0 = __float2bfloat16(v0), h1 = __float2bfloat16(v1);
            *(__nv_bfloat162*)&g_ah[idx] = __halves2bfloat162(h0, h1);
            *(__nv_bfloat162*)&g_al[idx] = __halves2bfloat162(
                __float2bfloat16(v0 - __bfloat162float(h0)),
                __float2bfloat16(v1 - __bfloat162float(h1)));
        }
    }
}

// ============================================================
extern "C" void kernel_launch(void* const* d_in, const int* in_sizes, int n_in,
                              void* d_out, int out_size) {
    const float* x      = (const float*)d_in[0];
    const int*   pmask  = (const int*)  d_in[1];
    const float* w_qkv  = (const float*)d_in[2];
    const float* w_o    = (const float*)d_in[3];
    float*       out    = (float*)d_out;

    cudaFuncSetAttribute(attn_kernel,
                         cudaFuncAttributeMaxDynamicSharedMemorySize, SMEM_ATTN);

    rope_table_kernel<<<256, 256>>>();
    split_kernel<0><<<(NROWS*DM/4 + 255)/256, 256>>>(x,     NROWS*DM/4);
    split_kernel<1><<<(N_QKV*DM/4 + 255)/256, 256>>>(w_qkv, N_QKV*DM/4);
    split_kernel<2><<<(DM*DM/4 + 255)/256, 256>>>(w_o,      DM*DM/4);

    gemm_mma<0><<<dim3(N_QKV/128, NROWS/128), 256, SMEM_GEMM>>>(nullptr);
    attn_kernel<<<dim3(SEQ/64, NH, BATCH), 256, SMEM_ATTN>>>(pmask);
    gemm_mma<1><<<dim3(DM/128, NROWS/128), 256, SMEM_GEMM>>>(out);
}